// round 1
// baseline (speedup 1.0000x reference)
#include <cuda_runtime.h>
#include <math.h>

#define M 4096
#define C 512
#define D 128
#define ALPHA 0.5f

// scratch (device globals; no runtime allocation allowed)
__device__ float g_S[M];       // sum_{c != label} exp(-d)
__device__ float g_pos[M];     // d at positive class
__device__ float g_counts[C];  // class counts
__device__ float g_sumx[C * D];// per-class x0 sums
__device__ int   g_labels[M];

// ---------------------------------------------------------------------------
__global__ void k_zero() {
    int i = blockIdx.x * blockDim.x + threadIdx.x;
    if (i < M) { g_S[i] = 0.0f; g_pos[i] = 0.0f; }
    if (i < C) g_counts[i] = 0.0f;
    if (i < C * D) g_sumx[i] = 0.0f;
}

// ---------------------------------------------------------------------------
// One warp per row: find label (argmax of exact one-hot), accumulate counts
// and per-class x0 sums.
__global__ void k_labels(const float* __restrict__ onehot,
                         const float* __restrict__ x0) {
    int row = blockIdx.x * 8 + (threadIdx.x >> 5);
    int lane = threadIdx.x & 31;
    if (row >= M) return;

    const float* oh = onehot + (size_t)row * C;
    int idx = 0;
#pragma unroll
    for (int j = 0; j < C / 32; j++) {
        float v = oh[lane + 32 * j];
        if (v > 0.5f) idx = lane + 32 * j;
    }
#pragma unroll
    for (int off = 16; off; off >>= 1)
        idx = max(idx, __shfl_xor_sync(0xffffffffu, idx, off));

    if (lane == 0) {
        g_labels[row] = idx;
        atomicAdd(&g_counts[idx], 1.0f);
    }
    const float* xr = x0 + (size_t)row * D;
#pragma unroll
    for (int j = 0; j < D / 32; j++)
        atomicAdd(&g_sumx[idx * D + lane + 32 * j], xr[lane + 32 * j]);
}

// ---------------------------------------------------------------------------
// L1 distance + partial loss sums.
// Block = 32 rows x 128 centers. 8 warps; each warp owns 4 rows, lanes split
// the 128 centers 4 ways (centers lane, lane+32, lane+64, lane+96).
#define BR 32
#define BC 128
#define TPB 256
#define SMC_STRIDE 129  // odd pad -> conflict-free center reads

__global__ void __launch_bounds__(TPB, 2)
k_dist(const float* __restrict__ x0, const float* __restrict__ centers) {
    extern __shared__ float sm[];
    float* smc = sm;                     // [BC][SMC_STRIDE]
    float* smx = sm + BC * SMC_STRIDE;   // [BR][D]

    int tid = threadIdx.x;
    int warp = tid >> 5, lane = tid & 31;
    int rbase = blockIdx.x * BR;
    int cbase = blockIdx.y * BC;

    // load x tile (linear, coalesced, conflict-free)
    {
        const float4* xg = (const float4*)(x0 + (size_t)rbase * D);
        float4* xs = (float4*)smx;
#pragma unroll
        for (int j = 0; j < (BR * D / 4) / TPB; j++)  // 4 iters
            xs[tid + j * TPB] = xg[tid + j * TPB];
    }
    // load center tile: warp handles 4 center rows, 8 lanes per row (coalesced
    // 128B segments); scalar STS with all-distinct banks.
    {
        int sub = lane >> 3, u = lane & 7;
#pragma unroll
        for (int cg = 0; cg < 4; cg++) {
#pragma unroll
            for (int ds = 0; ds < 4; ds++) {
                int c = cg * 32 + warp * 4 + sub;
                int d = ds * 32 + u * 4;
                float4 v = *(const float4*)(centers + (size_t)(cbase + c) * D + d);
                float* p = smc + c * SMC_STRIDE + d;
                p[0] = v.x; p[1] = v.y; p[2] = v.z; p[3] = v.w;
            }
        }
    }
    __syncthreads();

    float acc[4][4];
#pragma unroll
    for (int k = 0; k < 4; k++)
#pragma unroll
        for (int j = 0; j < 4; j++) acc[k][j] = 0.0f;

    const float* xrow = smx + (warp * 4) * D;

#pragma unroll 4
    for (int d = 0; d < D; d += 2) {
        float2 xv[4];
#pragma unroll
        for (int k = 0; k < 4; k++)
            xv[k] = *(const float2*)(xrow + k * D + d);  // broadcast
#pragma unroll
        for (int j = 0; j < 4; j++) {
            const float* cp = smc + (lane + 32 * j) * SMC_STRIDE + d;
            float c0 = cp[0], c1 = cp[1];
#pragma unroll
            for (int k = 0; k < 4; k++) {
                acc[k][j] += fabsf(xv[k].x - c0);
                acc[k][j] += fabsf(xv[k].y - c1);
            }
        }
    }

    // epilogue: per-row partial S and pos, warp-reduce, atomic accumulate
    int lab[4];
#pragma unroll
    for (int k = 0; k < 4; k++)
        lab[k] = g_labels[rbase + warp * 4 + k];

#pragma unroll
    for (int k = 0; k < 4; k++) {
        float S = 0.0f, pos = 0.0f;
#pragma unroll
        for (int j = 0; j < 4; j++) {
            int cg_ = cbase + lane + 32 * j;
            float dsum = acc[k][j];
            if (cg_ == lab[k]) pos += dsum;
            else S += __expf(-dsum);
        }
#pragma unroll
        for (int off = 16; off; off >>= 1) {
            S += __shfl_xor_sync(0xffffffffu, S, off);
            pos += __shfl_xor_sync(0xffffffffu, pos, off);
        }
        if (lane == 0) {
            int row = rbase + warp * 4 + k;
            atomicAdd(&g_S[row], S);
            atomicAdd(&g_pos[row], pos);
        }
    }
}

// ---------------------------------------------------------------------------
// Final: loss[i] = pos + log(1 + S); new_centers from counts/sums.
__global__ void k_final(const float* __restrict__ centers,
                        float* __restrict__ out) {
    int i = blockIdx.x * blockDim.x + threadIdx.x;
    if (i < M)
        out[i] = g_pos[i] + logf(1.0f + g_S[i]);
    if (i < C * D) {
        int c = i >> 7;  // D = 128
        float cnt = g_counts[c];
        float cv = centers[i];
        out[M + i] = cv - ALPHA * (cnt * cv - g_sumx[i]) / (cnt + 1.0f);
    }
}

// ---------------------------------------------------------------------------
extern "C" void kernel_launch(void* const* d_in, const int* in_sizes, int n_in,
                              void* d_out, int out_size) {
    // identify inputs by element count (all distinct)
    const float *x0 = nullptr, *onehot = nullptr, *centers = nullptr;
    for (int i = 0; i < n_in; i++) {
        if (in_sizes[i] == M * D) x0 = (const float*)d_in[i];
        else if (in_sizes[i] == M * C) onehot = (const float*)d_in[i];
        else if (in_sizes[i] == C * D) centers = (const float*)d_in[i];
    }
    float* out = (float*)d_out;

    static bool attr_set = false;
    int smem_bytes = (BC * SMC_STRIDE + BR * D) * (int)sizeof(float);
    // setting the attribute is idempotent/deterministic; do it every call
    cudaFuncSetAttribute(k_dist, cudaFuncAttributeMaxDynamicSharedMemorySize,
                         smem_bytes);
    (void)attr_set;

    k_zero<<<(C * D + 255) / 256, 256>>>();
    k_labels<<<M / 8, 256>>>(onehot, x0);
    dim3 grid(M / BR, C / BC);
    k_dist<<<grid, TPB, smem_bytes>>>(x0, centers);
    k_final<<<(C * D + 255) / 256, 256>>>(centers, out);
}